// round 3
// baseline (speedup 1.0000x reference)
#include <cuda_runtime.h>

// SSIM loss, fully fused:
//   kernel 1: per-tile separable Gaussian convs (5 fields) + SSIM map + block partial sum
//   kernel 2: deterministic reduction -> 1 - mean(ssim)
//
// Tile: 64x32 outputs, halo 74x42 (radius 5, zero padding).
// Horizontal-first with on-the-fly products (x,y read once per tap -> feeds
// x, y, x^2, y^2, xy accumulators). Vertical conv + epilogue fully in registers.

#define TW 64          // tile output width
#define TH 32          // tile output height
#define HW 74          // halo width  (TW + 10)
#define HH 42          // halo height (TH + 10)
#define SXS 76         // sx/sy smem row stride (mult of 4 -> 16B aligned float4)
#define HS 64          // H-buffer row stride
#define NTHREADS 256
#define GX 8           // 512/64
#define GY 16          // 512/32
#define GZ 48          // B*C
#define NBLOCKS (GX*GY*GZ)
#define SMEM_FLOATS (2*HH*SXS + 5*HH*HS)
#define SMEM_BYTES (SMEM_FLOATS * 4)

__device__ float g_partials[NBLOCKS];

// Gaussian weights (WINDOW=11, sigma=1.5), compile-time immediates for FFMA-imm.
#define KW_INIT { \
    0.00102838f, 0.00759876f, 0.03600077f, 0.10936069f, 0.21300546f, \
    0.26601173f, \
    0.21300546f, 0.10936069f, 0.03600077f, 0.00759876f, 0.00102838f }

__global__ void __launch_bounds__(NTHREADS, 2)
ssim_tile_kernel(const float* __restrict__ X, const float* __restrict__ Y)
{
    const float kW[11] = KW_INIT;

    extern __shared__ float smem[];
    float* sx   = smem;                 // [HH][SXS]
    float* sy   = smem + HH * SXS;      // [HH][SXS]
    float* Hbuf = smem + 2 * HH * SXS;  // [5][HH][HS]

    const int tid = threadIdx.x;
    const size_t base = (size_t)blockIdx.z * (512 * 512);
    const float* xb = X + base;
    const float* yb = Y + base;
    const int gy0 = blockIdx.y * TH - 5;
    const int gx0 = blockIdx.x * TW - 5;

    // ---- Phase 1: load halo tile (zero padding outside image) ----
    for (int i = tid; i < HH * SXS; i += NTHREADS) {
        int r = i / SXS;
        int c = i - r * SXS;
        float xv = 0.f, yv = 0.f;
        if (c < HW) {
            int gr = gy0 + r;
            int gc = gx0 + c;
            if ((unsigned)gr < 512u && (unsigned)gc < 512u) {
                int gi = (gr << 9) + gc;
                xv = __ldg(xb + gi);
                yv = __ldg(yb + gi);
            }
            sx[i] = xv;
            sy[i] = yv;
        } else {
            sx[i] = 0.f;   // keep padding defined (float4 reads may touch it)
            sy[i] = 0.f;
        }
    }
    __syncthreads();

    // ---- Phase 2: horizontal conv, 5 fields, products on the fly ----
    // 42 rows x 16 strips of 4 outputs = 672 items.
    for (int item = tid; item < HH * 16; item += NTHREADS) {
        int row = item >> 4;
        int xs  = (item & 15) << 2;           // output col base (mult of 4)
        const float4* px = (const float4*)(sx + row * SXS + xs);
        const float4* py = (const float4*)(sy + row * SXS + xs);
        float xv[16], yv[16];
        #pragma unroll
        for (int q = 0; q < 4; q++) {
            float4 a = px[q];
            float4 b = py[q];
            xv[4*q+0] = a.x; xv[4*q+1] = a.y; xv[4*q+2] = a.z; xv[4*q+3] = a.w;
            yv[4*q+0] = b.x; yv[4*q+1] = b.y; yv[4*q+2] = b.z; yv[4*q+3] = b.w;
        }
        float ax[4], ay[4], axx[4], ayy[4], axy[4];
        #pragma unroll
        for (int k = 0; k < 4; k++) {
            ax[k] = 0.f; ay[k] = 0.f; axx[k] = 0.f; ayy[k] = 0.f; axy[k] = 0.f;
        }
        #pragma unroll
        for (int j = 0; j < 14; j++) {
            float xj = xv[j], yj = yv[j];
            float xx = xj * xj;
            float yy = yj * yj;
            float xy = xj * yj;
            #pragma unroll
            for (int k = 0; k < 4; k++) {
                int t = j - k;
                if (t >= 0 && t < 11) {
                    float w = kW[t];
                    ax[k]  = fmaf(w, xj, ax[k]);
                    ay[k]  = fmaf(w, yj, ay[k]);
                    axx[k] = fmaf(w, xx, axx[k]);
                    ayy[k] = fmaf(w, yy, ayy[k]);
                    axy[k] = fmaf(w, xy, axy[k]);
                }
            }
        }
        int o = row * HS + xs;   // mult of 4 -> 16B aligned
        *(float4*)(Hbuf + 0 * HH * HS + o) = make_float4(ax[0],  ax[1],  ax[2],  ax[3]);
        *(float4*)(Hbuf + 1 * HH * HS + o) = make_float4(ay[0],  ay[1],  ay[2],  ay[3]);
        *(float4*)(Hbuf + 2 * HH * HS + o) = make_float4(axx[0], axx[1], axx[2], axx[3]);
        *(float4*)(Hbuf + 3 * HH * HS + o) = make_float4(ayy[0], ayy[1], ayy[2], ayy[3]);
        *(float4*)(Hbuf + 4 * HH * HS + o) = make_float4(axy[0], axy[1], axy[2], axy[3]);
    }
    __syncthreads();

    // ---- Phase 3: vertical conv (strip of 8 rows) + SSIM epilogue ----
    // 64 cols x 4 strips = 256 items = exactly one per thread.
    const int col = tid & 63;
    const int r0  = (tid >> 6) << 3;   // 0,8,16,24
    float A[8], B[8], C[8], D[8], E[8];
    #pragma unroll
    for (int k = 0; k < 8; k++) { A[k]=0.f; B[k]=0.f; C[k]=0.f; D[k]=0.f; E[k]=0.f; }

    const float* h0 = Hbuf + r0 * HS + col;
    #pragma unroll
    for (int j = 0; j < 18; j++) {
        float vx  = h0[j * HS + 0 * HH * HS];
        float vy  = h0[j * HS + 1 * HH * HS];
        float vxx = h0[j * HS + 2 * HH * HS];
        float vyy = h0[j * HS + 3 * HH * HS];
        float vxy = h0[j * HS + 4 * HH * HS];
        #pragma unroll
        for (int k = 0; k < 8; k++) {
            int t = j - k;
            if (t >= 0 && t < 11) {
                float w = kW[t];
                A[k] = fmaf(w, vx,  A[k]);
                B[k] = fmaf(w, vy,  B[k]);
                C[k] = fmaf(w, vxx, C[k]);
                D[k] = fmaf(w, vyy, D[k]);
                E[k] = fmaf(w, vxy, E[k]);
            }
        }
    }

    float lsum = 0.f;
    #pragma unroll
    for (int k = 0; k < 8; k++) {
        float mux = A[k], muy = B[k];
        float mux2 = mux * mux;
        float muy2 = muy * muy;
        float muxy = mux * muy;
        float sxx = C[k] - mux2;
        float syy = D[k] - muy2;
        float sxy = E[k] - muxy;
        float num = (2.f * muxy + 1e-4f) * (2.f * sxy + 9e-4f);
        float den = (mux2 + muy2 + 1e-4f) * (sxx + syy + 9e-4f) + 1e-8f;
        lsum += __fdividef(num, den);
    }

    // ---- Block reduction (deterministic) ----
    #pragma unroll
    for (int o = 16; o > 0; o >>= 1)
        lsum += __shfl_xor_sync(0xffffffffu, lsum, o);
    __shared__ float wsum[8];
    if ((tid & 31) == 0) wsum[tid >> 5] = lsum;
    __syncthreads();
    if (tid == 0) {
        float s = 0.f;
        #pragma unroll
        for (int w = 0; w < 8; w++) s += wsum[w];
        g_partials[(blockIdx.z * GY + blockIdx.y) * GX + blockIdx.x] = s;
    }
}

__global__ void ssim_reduce_kernel(float* __restrict__ out)
{
    __shared__ double sm[256];
    double s = 0.0;
    for (int i = threadIdx.x; i < NBLOCKS; i += 256)
        s += (double)g_partials[i];
    sm[threadIdx.x] = s;
    __syncthreads();
    for (int st = 128; st > 0; st >>= 1) {
        if (threadIdx.x < st) sm[threadIdx.x] += sm[threadIdx.x + st];
        __syncthreads();
    }
    if (threadIdx.x == 0)
        out[0] = (float)(1.0 - sm[0] / (double)((double)GZ * 512.0 * 512.0));
}

extern "C" void kernel_launch(void* const* d_in, const int* in_sizes, int n_in,
                              void* d_out, int out_size)
{
    const float* x = (const float*)d_in[0];
    const float* y = (const float*)d_in[1];
    float* out = (float*)d_out;

    cudaFuncSetAttribute(ssim_tile_kernel,
                         cudaFuncAttributeMaxDynamicSharedMemorySize, SMEM_BYTES);
    dim3 grid(GX, GY, GZ);
    ssim_tile_kernel<<<grid, NTHREADS, SMEM_BYTES>>>(x, y);
    ssim_reduce_kernel<<<1, 256>>>(out);
}

// round 4
// speedup vs baseline: 1.0122x; 1.0122x over previous
#include <cuda_runtime.h>

// SSIM loss, fully fused:
//   kernel 1: per-tile separable Gaussian convs (5 fields) + SSIM map + block partial sum
//   kernel 2: deterministic reduction -> 1 - mean(ssim)
//
// Tile: 64x32 outputs, halo 74x42 (radius 5, zero padding).
// Horizontal-first with on-the-fly products (x,y read once per tap -> feeds
// x, y, x^2, y^2, xy accumulators). Vertical conv + epilogue fully in registers.

#define TW 64          // tile output width
#define TH 32          // tile output height
#define HW 74          // halo width  (TW + 10)
#define HH 42          // halo height (TH + 10)
#define SXS 76         // sx/sy smem row stride (mult of 4 -> 16B aligned float4)
#define HS 64          // H-buffer row stride
#define NTHREADS 256
#define GX 8           // 512/64
#define GY 16          // 512/32
#define GZ 48          // B*C
#define NBLOCKS (GX*GY*GZ)
#define SMEM_FLOATS (2*HH*SXS + 5*HH*HS)
#define SMEM_BYTES (SMEM_FLOATS * 4)

__device__ float g_partials[NBLOCKS];

// Gaussian weights (WINDOW=11, sigma=1.5), compile-time immediates for FFMA-imm.
#define KW_INIT { \
    0.00102838f, 0.00759876f, 0.03600077f, 0.10936069f, 0.21300546f, \
    0.26601173f, \
    0.21300546f, 0.10936069f, 0.03600077f, 0.00759876f, 0.00102838f }

__global__ void __launch_bounds__(NTHREADS, 2)
ssim_tile_kernel(const float* __restrict__ X, const float* __restrict__ Y)
{
    const float kW[11] = KW_INIT;

    extern __shared__ float smem[];
    float* sx   = smem;                 // [HH][SXS]
    float* sy   = smem + HH * SXS;      // [HH][SXS]
    float* Hbuf = smem + 2 * HH * SXS;  // [5][HH][HS]

    const int tid = threadIdx.x;
    const size_t base = (size_t)blockIdx.z * (512 * 512);
    const float* xb = X + base;
    const float* yb = Y + base;
    const int gy0 = blockIdx.y * TH - 5;
    const int gx0 = blockIdx.x * TW - 5;

    // ---- Phase 1: load halo tile (zero padding outside image) ----
    for (int i = tid; i < HH * SXS; i += NTHREADS) {
        int r = i / SXS;
        int c = i - r * SXS;
        float xv = 0.f, yv = 0.f;
        if (c < HW) {
            int gr = gy0 + r;
            int gc = gx0 + c;
            if ((unsigned)gr < 512u && (unsigned)gc < 512u) {
                int gi = (gr << 9) + gc;
                xv = __ldg(xb + gi);
                yv = __ldg(yb + gi);
            }
            sx[i] = xv;
            sy[i] = yv;
        } else {
            sx[i] = 0.f;   // keep padding defined (float4 reads may touch it)
            sy[i] = 0.f;
        }
    }
    __syncthreads();

    // ---- Phase 2: horizontal conv, 5 fields, products on the fly ----
    // 42 rows x 16 strips of 4 outputs = 672 items.
    for (int item = tid; item < HH * 16; item += NTHREADS) {
        int row = item >> 4;
        int xs  = (item & 15) << 2;           // output col base (mult of 4)
        const float4* px = (const float4*)(sx + row * SXS + xs);
        const float4* py = (const float4*)(sy + row * SXS + xs);
        float xv[16], yv[16];
        #pragma unroll
        for (int q = 0; q < 4; q++) {
            float4 a = px[q];
            float4 b = py[q];
            xv[4*q+0] = a.x; xv[4*q+1] = a.y; xv[4*q+2] = a.z; xv[4*q+3] = a.w;
            yv[4*q+0] = b.x; yv[4*q+1] = b.y; yv[4*q+2] = b.z; yv[4*q+3] = b.w;
        }
        float ax[4], ay[4], axx[4], ayy[4], axy[4];
        #pragma unroll
        for (int k = 0; k < 4; k++) {
            ax[k] = 0.f; ay[k] = 0.f; axx[k] = 0.f; ayy[k] = 0.f; axy[k] = 0.f;
        }
        #pragma unroll
        for (int j = 0; j < 14; j++) {
            float xj = xv[j], yj = yv[j];
            float xx = xj * xj;
            float yy = yj * yj;
            float xy = xj * yj;
            #pragma unroll
            for (int k = 0; k < 4; k++) {
                int t = j - k;
                if (t >= 0 && t < 11) {
                    float w = kW[t];
                    ax[k]  = fmaf(w, xj, ax[k]);
                    ay[k]  = fmaf(w, yj, ay[k]);
                    axx[k] = fmaf(w, xx, axx[k]);
                    ayy[k] = fmaf(w, yy, ayy[k]);
                    axy[k] = fmaf(w, xy, axy[k]);
                }
            }
        }
        int o = row * HS + xs;   // mult of 4 -> 16B aligned
        *(float4*)(Hbuf + 0 * HH * HS + o) = make_float4(ax[0],  ax[1],  ax[2],  ax[3]);
        *(float4*)(Hbuf + 1 * HH * HS + o) = make_float4(ay[0],  ay[1],  ay[2],  ay[3]);
        *(float4*)(Hbuf + 2 * HH * HS + o) = make_float4(axx[0], axx[1], axx[2], axx[3]);
        *(float4*)(Hbuf + 3 * HH * HS + o) = make_float4(ayy[0], ayy[1], ayy[2], ayy[3]);
        *(float4*)(Hbuf + 4 * HH * HS + o) = make_float4(axy[0], axy[1], axy[2], axy[3]);
    }
    __syncthreads();

    // ---- Phase 3: vertical conv (strip of 8 rows) + SSIM epilogue ----
    // 64 cols x 4 strips = 256 items = exactly one per thread.
    const int col = tid & 63;
    const int r0  = (tid >> 6) << 3;   // 0,8,16,24
    float A[8], B[8], C[8], D[8], E[8];
    #pragma unroll
    for (int k = 0; k < 8; k++) { A[k]=0.f; B[k]=0.f; C[k]=0.f; D[k]=0.f; E[k]=0.f; }

    const float* h0 = Hbuf + r0 * HS + col;
    #pragma unroll
    for (int j = 0; j < 18; j++) {
        float vx  = h0[j * HS + 0 * HH * HS];
        float vy  = h0[j * HS + 1 * HH * HS];
        float vxx = h0[j * HS + 2 * HH * HS];
        float vyy = h0[j * HS + 3 * HH * HS];
        float vxy = h0[j * HS + 4 * HH * HS];
        #pragma unroll
        for (int k = 0; k < 8; k++) {
            int t = j - k;
            if (t >= 0 && t < 11) {
                float w = kW[t];
                A[k] = fmaf(w, vx,  A[k]);
                B[k] = fmaf(w, vy,  B[k]);
                C[k] = fmaf(w, vxx, C[k]);
                D[k] = fmaf(w, vyy, D[k]);
                E[k] = fmaf(w, vxy, E[k]);
            }
        }
    }

    float lsum = 0.f;
    #pragma unroll
    for (int k = 0; k < 8; k++) {
        float mux = A[k], muy = B[k];
        float mux2 = mux * mux;
        float muy2 = muy * muy;
        float muxy = mux * muy;
        float sxx = C[k] - mux2;
        float syy = D[k] - muy2;
        float sxy = E[k] - muxy;
        float num = (2.f * muxy + 1e-4f) * (2.f * sxy + 9e-4f);
        float den = (mux2 + muy2 + 1e-4f) * (sxx + syy + 9e-4f) + 1e-8f;
        lsum += __fdividef(num, den);
    }

    // ---- Block reduction (deterministic) ----
    #pragma unroll
    for (int o = 16; o > 0; o >>= 1)
        lsum += __shfl_xor_sync(0xffffffffu, lsum, o);
    __shared__ float wsum[8];
    if ((tid & 31) == 0) wsum[tid >> 5] = lsum;
    __syncthreads();
    if (tid == 0) {
        float s = 0.f;
        #pragma unroll
        for (int w = 0; w < 8; w++) s += wsum[w];
        g_partials[(blockIdx.z * GY + blockIdx.y) * GX + blockIdx.x] = s;
    }
}

__global__ void ssim_reduce_kernel(float* __restrict__ out)
{
    __shared__ double sm[256];
    double s = 0.0;
    for (int i = threadIdx.x; i < NBLOCKS; i += 256)
        s += (double)g_partials[i];
    sm[threadIdx.x] = s;
    __syncthreads();
    for (int st = 128; st > 0; st >>= 1) {
        if (threadIdx.x < st) sm[threadIdx.x] += sm[threadIdx.x + st];
        __syncthreads();
    }
    if (threadIdx.x == 0)
        out[0] = (float)(1.0 - sm[0] / (double)((double)GZ * 512.0 * 512.0));
}

extern "C" void kernel_launch(void* const* d_in, const int* in_sizes, int n_in,
                              void* d_out, int out_size)
{
    const float* x = (const float*)d_in[0];
    const float* y = (const float*)d_in[1];
    float* out = (float*)d_out;

    cudaFuncSetAttribute(ssim_tile_kernel,
                         cudaFuncAttributeMaxDynamicSharedMemorySize, SMEM_BYTES);
    dim3 grid(GX, GY, GZ);
    ssim_tile_kernel<<<grid, NTHREADS, SMEM_BYTES>>>(x, y);
    ssim_reduce_kernel<<<1, 256>>>(out);
}

// round 5
// speedup vs baseline: 2.1660x; 2.1398x over previous
#include <cuda_runtime.h>

// SSIM loss, separable Gaussian (11x11, sigma=1.5), fully fused.
//   kernel 1: horizontal conv straight from GMEM (aligned float4 windows,
//             products on the fly, f32x2-packed accumulators) -> smem H-buffer
//             -> vertical conv + SSIM epilogue in registers -> block partial.
//   kernel 2: deterministic two-level reduction -> 1 - mean(ssim).

#define TW 64
#define TH 32
#define HH 42              // TH + 10 halo rows
#define NTHREADS 256
#define GX 8               // 512/TW
#define GY 16              // 512/TH
#define GZ 48              // B*C
#define NBLOCKS (GX*GY*GZ)

// H-buffer: P1 = (hx,hy) pairs [HH][64 pairs], P2 = (hxx,hyy) pairs, P3 = hxy scalar
#define P2_OFF (HH*128)
#define P3_OFF (2*HH*128)
#define SMEM_FLOATS (2*HH*128 + HH*64)
#define SMEM_BYTES (SMEM_FLOATS*4)      // 53760 B

__device__ float g_partials[NBLOCKS];

#define KW_INIT { \
    0.00102838f, 0.00759876f, 0.03600077f, 0.10936069f, 0.21300546f, \
    0.26601173f, \
    0.21300546f, 0.10936069f, 0.03600077f, 0.00759876f, 0.00102838f }

__device__ __forceinline__ unsigned long long f2_pack(float lo, float hi) {
    unsigned long long d;
    asm("mov.b64 %0, {%1, %2};" : "=l"(d) : "r"(__float_as_uint(lo)), "r"(__float_as_uint(hi)));
    return d;
}
__device__ __forceinline__ void f2_unpack(unsigned long long v, float& lo, float& hi) {
    unsigned int a, b;
    asm("mov.b64 {%0, %1}, %2;" : "=r"(a), "=r"(b) : "l"(v));
    lo = __uint_as_float(a); hi = __uint_as_float(b);
}
__device__ __forceinline__ unsigned long long f2_fma(unsigned long long a,
                                                     unsigned long long b,
                                                     unsigned long long c) {
    unsigned long long d;
    asm("fma.rn.f32x2 %0, %1, %2, %3;" : "=l"(d) : "l"(a), "l"(b), "l"(c));
    return d;
}
__device__ __forceinline__ unsigned long long f2_mul(unsigned long long a,
                                                     unsigned long long b) {
    unsigned long long d;
    asm("mul.rn.f32x2 %0, %1, %2;" : "=l"(d) : "l"(a), "l"(b));
    return d;
}

__global__ void __launch_bounds__(NTHREADS, 3)
ssim_tile_kernel(const float* __restrict__ X, const float* __restrict__ Y)
{
    const float kW[11] = KW_INIT;
    unsigned long long kW2[11];
    #pragma unroll
    for (int t = 0; t < 11; t++) kW2[t] = f2_pack(kW[t], kW[t]);

    extern __shared__ float Hbuf[];

    const int tid = threadIdx.x;
    const size_t base = (size_t)blockIdx.z << 18;
    const float* xb = X + base;
    const float* yb = Y + base;
    const int gy0 = blockIdx.y * TH - 5;
    const int cbase = blockIdx.x * TW;

    // ---- Phase A: horizontal conv from GMEM, 5 fields, packed accumulators ----
    // Item = (halo row, 4-wide output strip). 42 * 16 = 672 items.
    for (int item = tid; item < HH * 16; item += NTHREADS) {
        int row = item >> 4;
        int xs  = (item & 15) << 2;
        int gr  = gy0 + row;
        int a0  = cbase + xs - 8;           // aligned float4 window base
        bool rok = ((unsigned)gr < 512u);
        const float* xr = xb + ((size_t)(gr & 511) << 9);
        const float* yr = yb + ((size_t)(gr & 511) << 9);

        float xv[20], yv[20];
        #pragma unroll
        for (int q = 0; q < 5; q++) {
            int c = a0 + 4 * q;
            float4 xa, ya;
            if (rok && (unsigned)c < 512u) {
                xa = *(const float4*)(xr + c);
                ya = *(const float4*)(yr + c);
            } else {
                xa = make_float4(0.f, 0.f, 0.f, 0.f);
                ya = xa;
            }
            xv[4*q+0]=xa.x; xv[4*q+1]=xa.y; xv[4*q+2]=xa.z; xv[4*q+3]=xa.w;
            yv[4*q+0]=ya.x; yv[4*q+1]=ya.y; yv[4*q+2]=ya.z; yv[4*q+3]=ya.w;
        }

        unsigned long long Pxy[4], Pqq[4];
        float axy[4];
        #pragma unroll
        for (int k = 0; k < 4; k++) { Pxy[k] = 0ull; Pqq[k] = 0ull; axy[k] = 0.f; }

        // output col c0+k uses input index j = k + t + 3, t in [0,10]
        #pragma unroll
        for (int j = 3; j < 17; j++) {
            unsigned long long pxy = f2_pack(xv[j], yv[j]);    // (x, y)
            unsigned long long pqq = f2_mul(pxy, pxy);         // (x^2, y^2)
            float xy = xv[j] * yv[j];
            #pragma unroll
            for (int k = 0; k < 4; k++) {
                int t = j - 3 - k;
                if (t >= 0 && t < 11) {
                    Pxy[k] = f2_fma(kW2[t], pxy, Pxy[k]);
                    Pqq[k] = f2_fma(kW2[t], pqq, Pqq[k]);
                    axy[k] = fmaf(kW[t], xy, axy[k]);
                }
            }
        }

        float* p1 = Hbuf + row * 128 + xs * 2;      // pair-interleaved
        *(ulonglong2*)(p1)     = make_ulonglong2(Pxy[0], Pxy[1]);
        *(ulonglong2*)(p1 + 4) = make_ulonglong2(Pxy[2], Pxy[3]);
        float* p2 = p1 + P2_OFF;
        *(ulonglong2*)(p2)     = make_ulonglong2(Pqq[0], Pqq[1]);
        *(ulonglong2*)(p2 + 4) = make_ulonglong2(Pqq[2], Pqq[3]);
        *(float4*)(Hbuf + P3_OFF + row * 64 + xs) =
            make_float4(axy[0], axy[1], axy[2], axy[3]);
    }
    __syncthreads();

    // ---- Phase B: vertical conv (8-row strip) + SSIM epilogue ----
    const int col = tid & 63;
    const int r0  = (tid >> 6) << 3;    // 0,8,16,24

    unsigned long long AB[8], CD[8];
    float E[8];
    #pragma unroll
    for (int k = 0; k < 8; k++) { AB[k] = 0ull; CD[k] = 0ull; E[k] = 0.f; }

    const float* q1 = Hbuf + r0 * 128 + 2 * col;
    const float* q3 = Hbuf + P3_OFF + r0 * 64 + col;
    #pragma unroll
    for (int j = 0; j < 18; j++) {
        unsigned long long v1 = *(const unsigned long long*)(q1 + j * 128);
        unsigned long long v2 = *(const unsigned long long*)(q1 + j * 128 + P2_OFF);
        float v3 = q3[j * 64];
        #pragma unroll
        for (int k = 0; k < 8; k++) {
            int t = j - k;
            if (t >= 0 && t < 11) {
                AB[k] = f2_fma(kW2[t], v1, AB[k]);
                CD[k] = f2_fma(kW2[t], v2, CD[k]);
                E[k]  = fmaf(kW[t], v3, E[k]);
            }
        }
    }

    float lsum = 0.f;
    #pragma unroll
    for (int k = 0; k < 8; k++) {
        float mux, muy, sxxr, syyr;
        f2_unpack(AB[k], mux, muy);
        f2_unpack(CD[k], sxxr, syyr);
        float mux2 = mux * mux;
        float muy2 = muy * muy;
        float muxy = mux * muy;
        float sxx = sxxr - mux2;
        float syy = syyr - muy2;
        float sxy = E[k] - muxy;
        float num = (2.f * muxy + 1e-4f) * (2.f * sxy + 9e-4f);
        float den = (mux2 + muy2 + 1e-4f) * (sxx + syy + 9e-4f) + 1e-8f;
        lsum += __fdividef(num, den);
    }

    // ---- Deterministic block reduction ----
    #pragma unroll
    for (int o = 16; o > 0; o >>= 1)
        lsum += __shfl_xor_sync(0xffffffffu, lsum, o);
    __shared__ float wsum[8];
    if ((tid & 31) == 0) wsum[tid >> 5] = lsum;
    __syncthreads();
    if (tid == 0) {
        float s = 0.f;
        #pragma unroll
        for (int w = 0; w < 8; w++) s += wsum[w];
        g_partials[(blockIdx.z * GY + blockIdx.y) * GX + blockIdx.x] = s;
    }
}

__global__ void ssim_reduce_kernel(float* __restrict__ out)
{
    __shared__ double sm[32];
    double s = 0.0;
    #pragma unroll
    for (int i = threadIdx.x; i < NBLOCKS; i += 1024)
        s += (double)g_partials[i];
    #pragma unroll
    for (int o = 16; o > 0; o >>= 1)
        s += __shfl_xor_sync(0xffffffffu, s, o);
    if ((threadIdx.x & 31) == 0) sm[threadIdx.x >> 5] = s;
    __syncthreads();
    if (threadIdx.x < 32) {
        double t = sm[threadIdx.x];
        #pragma unroll
        for (int o = 16; o > 0; o >>= 1)
            t += __shfl_xor_sync(0xffffffffu, t, o);
        if (threadIdx.x == 0)
            out[0] = (float)(1.0 - t / 12582912.0);
    }
}

extern "C" void kernel_launch(void* const* d_in, const int* in_sizes, int n_in,
                              void* d_out, int out_size)
{
    const float* x = (const float*)d_in[0];
    const float* y = (const float*)d_in[1];
    float* out = (float*)d_out;

    cudaFuncSetAttribute(ssim_tile_kernel,
                         cudaFuncAttributeMaxDynamicSharedMemorySize, SMEM_BYTES);
    dim3 grid(GX, GY, GZ);
    ssim_tile_kernel<<<grid, NTHREADS, SMEM_BYTES>>>(x, y);
    ssim_reduce_kernel<<<1, 1024>>>(out);
}

// round 6
// speedup vs baseline: 2.9677x; 1.3701x over previous
#include <cuda_runtime.h>

// SSIM loss, separable Gaussian (11x11, sigma=1.5), single fused kernel.
//
// Field reduction: with u=x+y, v=x-y and U,V,P,Q = conv(u),conv(v),conv(u^2),conv(v^2):
//   mux^2+muy^2 = (U^2+V^2)/2        2*mu_xy = (U^2-V^2)/2
//   Cxx+Cyy     = (P+Q)/2            2*Cxy   = (P-Q)/2
// -> only 4 conv fields, packed as two f32x2 pairs (U,V) and (P,Q).
//
// Horizontal conv straight from GMEM (aligned float4 windows) -> smem H-buffer
// -> vertical conv + SSIM epilogue in registers -> block partial -> fused
// deterministic-enough (double) atomic reduction, last block finalizes.

#define TW 64
#define TH 32
#define HH 42              // TH + 10 halo rows
#define NTHREADS 256
#define GX 8               // 512/TW
#define GY 16              // 512/TH
#define GZ 48              // B*C
#define NBLOCKS (GX*GY*GZ)

// H-buffer: P1 = (U,V) pairs [HH][64 pairs], P2 = (P,Q) pairs
#define P2_OFF (HH*128)
#define SMEM_FLOATS (2*HH*128)
#define SMEM_BYTES (SMEM_FLOATS*4)      // 43008 B

__device__ double       g_accum;   // zero-init at module load; reset by last block
__device__ unsigned int g_count;

// Gaussian half-window (symmetric: w[t] = w[10-t])
#define W0 0.00102838f
#define W1 0.00759876f
#define W2 0.03600077f
#define W3 0.10936069f
#define W4 0.21300546f
#define W5 0.26601173f
#define KT(t) ((t) < 6 ? (t) : 10 - (t))

__device__ __forceinline__ unsigned long long f2_pack(float lo, float hi) {
    unsigned long long d;
    asm("mov.b64 %0, {%1, %2};" : "=l"(d) : "r"(__float_as_uint(lo)), "r"(__float_as_uint(hi)));
    return d;
}
__device__ __forceinline__ void f2_unpack(unsigned long long v, float& lo, float& hi) {
    unsigned int a, b;
    asm("mov.b64 {%0, %1}, %2;" : "=r"(a), "=r"(b) : "l"(v));
    lo = __uint_as_float(a); hi = __uint_as_float(b);
}
__device__ __forceinline__ unsigned long long f2_fma(unsigned long long a,
                                                     unsigned long long b,
                                                     unsigned long long c) {
    unsigned long long d;
    asm("fma.rn.f32x2 %0, %1, %2, %3;" : "=l"(d) : "l"(a), "l"(b), "l"(c));
    return d;
}
__device__ __forceinline__ unsigned long long f2_mul(unsigned long long a,
                                                     unsigned long long b) {
    unsigned long long d;
    asm("mul.rn.f32x2 %0, %1, %2;" : "=l"(d) : "l"(a), "l"(b));
    return d;
}

__global__ void __launch_bounds__(NTHREADS, 3)
ssim_fused_kernel(const float* __restrict__ X, const float* __restrict__ Y,
                  float* __restrict__ out)
{
    // 6 unique packed weights (symmetry)
    unsigned long long kw2[6];
    kw2[0] = f2_pack(W0, W0); kw2[1] = f2_pack(W1, W1); kw2[2] = f2_pack(W2, W2);
    kw2[3] = f2_pack(W3, W3); kw2[4] = f2_pack(W4, W4); kw2[5] = f2_pack(W5, W5);

    extern __shared__ float Hbuf[];

    const int tid = threadIdx.x;
    const size_t base = (size_t)blockIdx.z << 18;
    const float* xb = X + base;
    const float* yb = Y + base;
    const int gy0 = blockIdx.y * TH - 5;
    const int cbase = blockIdx.x * TW;

    // ---- Phase A: horizontal conv from GMEM, 2 packed fields ----
    // Item = (halo row, 4-wide output strip). 42 * 16 = 672 items.
    for (int item = tid; item < HH * 16; item += NTHREADS) {
        int row = item >> 4;
        int xs  = (item & 15) << 2;
        int gr  = gy0 + row;
        int a0  = cbase + xs - 8;           // aligned float4 window base
        bool rok = ((unsigned)gr < 512u);
        const float* xr = xb + ((size_t)(gr & 511) << 9);
        const float* yr = yb + ((size_t)(gr & 511) << 9);

        float xv[20], yv[20];
        #pragma unroll
        for (int q = 0; q < 5; q++) {
            int c = a0 + 4 * q;
            float4 xa, ya;
            if (rok && (unsigned)c < 512u) {
                xa = *(const float4*)(xr + c);
                ya = *(const float4*)(yr + c);
            } else {
                xa = make_float4(0.f, 0.f, 0.f, 0.f);
                ya = xa;
            }
            xv[4*q+0]=xa.x; xv[4*q+1]=xa.y; xv[4*q+2]=xa.z; xv[4*q+3]=xa.w;
            yv[4*q+0]=ya.x; yv[4*q+1]=ya.y; yv[4*q+2]=ya.z; yv[4*q+3]=ya.w;
        }

        unsigned long long Puv[4], Pqq[4];
        #pragma unroll
        for (int k = 0; k < 4; k++) { Puv[k] = 0ull; Pqq[k] = 0ull; }

        // output col c0+k uses input index j = k + t + 3, t in [0,10]
        #pragma unroll
        for (int j = 3; j < 17; j++) {
            float u = xv[j] + yv[j];
            float v = xv[j] - yv[j];
            unsigned long long p = f2_pack(u, v);     // (u, v)
            unsigned long long q = f2_mul(p, p);      // (u^2, v^2)
            #pragma unroll
            for (int k = 0; k < 4; k++) {
                int t = j - 3 - k;
                if (t >= 0 && t < 11) {
                    Puv[k] = f2_fma(kw2[KT(t)], p, Puv[k]);
                    Pqq[k] = f2_fma(kw2[KT(t)], q, Pqq[k]);
                }
            }
        }

        float* p1 = Hbuf + row * 128 + xs * 2;      // pair-interleaved
        *(ulonglong2*)(p1)     = make_ulonglong2(Puv[0], Puv[1]);
        *(ulonglong2*)(p1 + 4) = make_ulonglong2(Puv[2], Puv[3]);
        float* p2 = p1 + P2_OFF;
        *(ulonglong2*)(p2)     = make_ulonglong2(Pqq[0], Pqq[1]);
        *(ulonglong2*)(p2 + 4) = make_ulonglong2(Pqq[2], Pqq[3]);
    }
    __syncthreads();

    // ---- Phase B: vertical conv (8-row strip) + SSIM epilogue ----
    const int col = tid & 63;
    const int r0  = (tid >> 6) << 3;    // 0,8,16,24

    unsigned long long AB[8], CD[8];
    #pragma unroll
    for (int k = 0; k < 8; k++) { AB[k] = 0ull; CD[k] = 0ull; }

    const float* q1 = Hbuf + r0 * 128 + 2 * col;
    #pragma unroll
    for (int j = 0; j < 18; j++) {
        unsigned long long v1 = *(const unsigned long long*)(q1 + j * 128);
        unsigned long long v2 = *(const unsigned long long*)(q1 + j * 128 + P2_OFF);
        #pragma unroll
        for (int k = 0; k < 8; k++) {
            int t = j - k;
            if (t >= 0 && t < 11) {
                AB[k] = f2_fma(kw2[KT(t)], v1, AB[k]);
                CD[k] = f2_fma(kw2[KT(t)], v2, CD[k]);
            }
        }
    }

    float lsum = 0.f;
    #pragma unroll
    for (int k = 0; k < 8; k++) {
        float U2, V2, Pk, Qk;
        unsigned long long sq = f2_mul(AB[k], AB[k]);   // (U^2, V^2)
        f2_unpack(sq, U2, V2);
        f2_unpack(CD[k], Pk, Qk);
        float m2     = 0.5f * (U2 + V2);   // mux^2 + muy^2
        float t1     = 0.5f * (U2 - V2);   // 2*mu_xy
        float Ps     = 0.5f * (Pk + Qk);   // Cxx + Cyy
        float Pd     = 0.5f * (Pk - Qk);   // 2*Cxy
        float sig2   = Pd - t1;            // 2*sigma_xy
        float sigsum = Ps - m2;            // sigma_x2 + sigma_y2
        float num = (t1 + 1e-4f) * (sig2 + 9e-4f);
        float den = (m2 + 1e-4f) * (sigsum + 9e-4f) + 1e-8f;
        lsum += __fdividef(num, den);
    }

    // ---- Block reduction ----
    #pragma unroll
    for (int o = 16; o > 0; o >>= 1)
        lsum += __shfl_xor_sync(0xffffffffu, lsum, o);
    __shared__ float wsum[8];
    if ((tid & 31) == 0) wsum[tid >> 5] = lsum;
    __syncthreads();

    // ---- Fused global reduction: double atomic + arrival counter ----
    if (tid == 0) {
        float s = 0.f;
        #pragma unroll
        for (int w = 0; w < 8; w++) s += wsum[w];
        atomicAdd(&g_accum, (double)s);
        __threadfence();
        unsigned int prev = atomicAdd(&g_count, 1u);
        if (prev == NBLOCKS - 1u) {
            double tot = atomicAdd(&g_accum, 0.0);   // coherent read at L2
            out[0] = (float)(1.0 - tot / 12582912.0);
            // reset for next (graph-replayed) launch
            atomicExch((unsigned long long*)&g_accum, 0ull);
            atomicExch(&g_count, 0u);
        }
    }
}

extern "C" void kernel_launch(void* const* d_in, const int* in_sizes, int n_in,
                              void* d_out, int out_size)
{
    const float* x = (const float*)d_in[0];
    const float* y = (const float*)d_in[1];
    float* out = (float*)d_out;

    cudaFuncSetAttribute(ssim_fused_kernel,
                         cudaFuncAttributeMaxDynamicSharedMemorySize, SMEM_BYTES);
    dim3 grid(GX, GY, GZ);
    ssim_fused_kernel<<<grid, NTHREADS, SMEM_BYTES>>>(x, y, out);
}